// round 13
// baseline (speedup 1.0000x reference)
#include <cuda_runtime.h>
#include <cuda_bf16.h>
#include <cstdint>

#define Tt 512
#define Hh 512
#define Ff 256
#define Bb 256
#define NCTA 128
#define TPB  512

#define WSTR_E 776             // padded W row stride (elements); 1552 B
#define WSTR_B 1552
#define WHI_OFF 0
#define WLO_OFF (32 * WSTR_B)
#define A_OFF   (2 * 32 * WSTR_B)          // 99328
#define SA_STR  144                         // A row stride bytes (128B data + 16B pad)
#define CHUNKB  (32 * SA_STR)               // 4608
#define A_BYTES (24 * CHUNKB)               // 110592: whole step resident
#define RED_OFF (A_OFF + A_BYTES)           // 209920
#define MB_OFF  (RED_OFF + 16384)           // 226304 (4-way reduction area)
#define SM_DYN  (MB_OFF + 64)               // 226368

__device__ __align__(1024) __nv_bfloat16 g_xhi[(size_t)Bb * Tt * Ff];
__device__ __align__(1024) __nv_bfloat16 g_xlo[(size_t)Bb * Tt * Ff];
__device__ __align__(1024) __nv_bfloat16 g_hhi[2][Bb * Hh];
__device__ __align__(1024) __nv_bfloat16 g_hlo[2][Bb * Hh];
__device__ unsigned g_pflag[8 * 16 * 16];  // [mq][nq] producer flags, 64B apart
__device__ unsigned g_exit;

// ---------------- helpers ----------------
__device__ __forceinline__ uint32_t smem_u32(const void* p) {
    uint32_t a;
    asm("{ .reg .u64 t; cvta.to.shared.u64 t, %1; cvt.u32.u64 %0, t; }" : "=r"(a) : "l"(p));
    return a;
}
__device__ __forceinline__ void cp_async16(uint32_t dst, const void* src) {
    asm volatile("cp.async.cg.shared.global [%0], [%1], 16;" :: "r"(dst), "l"(src) : "memory");
}
__device__ __forceinline__ void mbar_init(uint32_t a, uint32_t c) {
    asm volatile("mbarrier.init.shared.b64 [%0], %1;" :: "r"(a), "r"(c) : "memory");
}
__device__ __forceinline__ void cpa_arrive(uint32_t a) {
    asm volatile("cp.async.mbarrier.arrive.noinc.shared.b64 [%0];" :: "r"(a) : "memory");
}
__device__ __forceinline__ void mbar_wait(uint32_t a, uint32_t par) {
    uint32_t done;
    do {
        asm volatile("{\n\t.reg .pred p;\n\t"
                     "mbarrier.try_wait.parity.shared::cta.b64 p, [%1], %2, 0x989680;\n\t"
                     "selp.b32 %0, 1, 0, p;\n\t}"
                     : "=r"(done) : "r"(a), "r"(par) : "memory");
    } while (!done);
}
__device__ __forceinline__ void ldm_x4(uint32_t& r0, uint32_t& r1, uint32_t& r2, uint32_t& r3,
                                       uint32_t addr) {
    asm volatile("ldmatrix.sync.aligned.m8n8.x4.shared.b16 {%0,%1,%2,%3}, [%4];"
                 : "=r"(r0), "=r"(r1), "=r"(r2), "=r"(r3) : "r"(addr));
}
__device__ __forceinline__ void mma16816(float* d, const uint32_t* a, uint32_t b0, uint32_t b1) {
    asm volatile("mma.sync.aligned.m16n8k16.row.col.f32.bf16.bf16.f32 "
                 "{%0,%1,%2,%3}, {%4,%5,%6,%7}, {%8,%9}, {%0,%1,%2,%3};"
                 : "+f"(d[0]), "+f"(d[1]), "+f"(d[2]), "+f"(d[3])
                 : "r"(a[0]), "r"(a[1]), "r"(a[2]), "r"(a[3]), "r"(b0), "r"(b1));
}
__device__ __forceinline__ uint32_t packbf(__nv_bfloat16 a, __nv_bfloat16 b) {
    return (uint32_t)__bfloat16_as_ushort(a) | ((uint32_t)__bfloat16_as_ushort(b) << 16);
}
__device__ __forceinline__ void stcg32(void* p, uint32_t v) {
    asm volatile("st.global.cg.b32 [%0], %1;" :: "l"(p), "r"(v) : "memory");
}
__device__ __forceinline__ float tanh_acc(float x) {
    float e = __expf(2.f * x);               // inf-safe
    return 1.f - __fdividef(2.f, e + 1.f);   // rcp.approx path
}

// ---------------- prep: split x into bf16 hi/lo ----------------
__global__ void xsplit(const float* __restrict__ x) {
    size_t base = ((size_t)blockIdx.x * 256 + threadIdx.x) * 8;
    float4 v0 = __ldg((const float4*)(x + base));
    float4 v1 = __ldg((const float4*)(x + base) + 1);
    float v[8] = {v0.x, v0.y, v0.z, v0.w, v1.x, v1.y, v1.z, v1.w};
    uint32_t ph[4], pl[4];
    #pragma unroll
    for (int j = 0; j < 4; j++) {
        __nv_bfloat16 h0 = __float2bfloat16(v[2*j]);
        __nv_bfloat16 h1 = __float2bfloat16(v[2*j+1]);
        __nv_bfloat16 l0 = __float2bfloat16(v[2*j]   - __bfloat162float(h0));
        __nv_bfloat16 l1 = __float2bfloat16(v[2*j+1] - __bfloat162float(h1));
        ph[j] = packbf(h0, h1); pl[j] = packbf(l0, l1);
    }
    *(uint4*)&g_xhi[base] = make_uint4(ph[0], ph[1], ph[2], ph[3]);
    *(uint4*)&g_xlo[base] = make_uint4(pl[0], pl[1], pl[2], pl[3]);
}

// chunk ids: 0-7 h_hi, 8-11 x_hi, 12-19 h_lo, 20-23 x_lo
__device__ __forceinline__ void compute_chunk(bool hi, int c, uint32_t aBase,
                                              uint32_t bHi, uint32_t bLo,
                                              float* D0a, float* D0b,
                                              float* D1a, float* D1b) {
    const uint32_t kg2 = (uint32_t)(hi ? c : c - 12) * 128;
    const uint32_t ab = aBase + (uint32_t)c * CHUNKB;
    #pragma unroll
    for (int k16 = 0; k16 < 4; k16++) {
        float* P0 = (k16 & 1) ? D0b : D0a;
        float* P1 = (k16 & 1) ? D1b : D1a;
        uint32_t a[4], b0, b1, b2, b3;
        ldm_x4(a[0], a[1], a[2], a[3], ab + k16 * 32);
        ldm_x4(b0, b1, b2, b3, bHi + kg2 + k16 * 32);
        mma16816(P0, a, b0, b1);
        mma16816(P1, a, b2, b3);
        if (hi) {
            ldm_x4(b0, b1, b2, b3, bLo + kg2 + k16 * 32);
            mma16816(P0, a, b0, b1);
            mma16816(P1, a, b2, b3);
        }
    }
}

// ---------------- persistent HMMA recurrence, 16 warps, 4-way K split ----------------
__global__ void __launch_bounds__(TPB, 1)
rnn_mma(const float* __restrict__ Wx, const float* __restrict__ Wh,
        const float* __restrict__ bias, const float* __restrict__ Wfc,
        const float* __restrict__ bfc, float* __restrict__ out)
{
    extern __shared__ char sm[];
    const uint32_t s0 = smem_u32(sm);

    const int tid  = threadIdx.x;
    const int wid  = tid >> 5, lane = tid & 31;
    const int grp  = wid >> 2;              // K-group 0..3
    const int qw   = wid & 3;               // quadrant within 32x32 tile
    const int mq   = blockIdx.x >> 4;
    const int nq   = blockIdx.x & 15;
    const int mbase = mq * 32, qn = nq * 32;
    const int m_off = (qw >> 1) * 16;
    const int n_off = (qw & 1) * 16;

    unsigned* myflag = &g_pflag[(mq * 16 + nq) * 16];
    unsigned* grpflags = &g_pflag[mq * 16 * 16];

    const uint32_t MBQ = s0 + MB_OFF;
    const uint32_t MBX = s0 + MB_OFF + 32;

    if (tid == 0) {
        #pragma unroll
        for (int i = 0; i < 4; i++) mbar_init(MBQ + 8 * i, 256);
        mbar_init(MBX, 256);
    }

    // resident [Wh;Wx] split slice: [n<32][k<768]
    __nv_bfloat16* sWhi = (__nv_bfloat16*)(sm + WHI_OFF);
    __nv_bfloat16* sWlo = (__nv_bfloat16*)(sm + WLO_OFF);
    for (int idx = tid; idx < 32 * 768; idx += TPB) {
        int n = idx / 768, k = idx - n * 768;
        float w = (k < 512) ? Wh[k * Hh + qn + n] : Wx[(k - 512) * Hh + qn + n];
        __nv_bfloat16 hi = __float2bfloat16(w);
        sWhi[n * WSTR_E + k] = hi;
        sWlo[n * WSTR_E + k] = __float2bfloat16(w - __bfloat162float(hi));
    }
    __syncthreads();   // mbar init + W visible

    const uint32_t aoff = (uint32_t)(m_off + (lane & 15)) * SA_STR + ((lane >> 4) << 4);
    const uint32_t boff = (uint32_t)(n_off + ((lane >> 4) << 3) + (lane & 7)) * WSTR_B
                        + (((lane >> 3) & 1) << 4);
    const uint32_t aBase = s0 + A_OFF + aoff;
    const uint32_t bHi   = s0 + WHI_OFF + boff;
    const uint32_t bLo   = s0 + WLO_OFF + boff;

    // producers: threads 0..255 only
    const int irow = (tid & 255) >> 3;
    const int iseg = tid & 7;
    const uint32_t pdst0 = s0 + A_OFF + (uint32_t)irow * SA_STR + (uint32_t)iseg * 16;
    const bool prod = (tid < 256);

    float* red = (float*)(sm + RED_OFF);

    // finalize-thread constants (512 threads, 2 outputs each)
    const int fi  = tid & 127;
    const int fq  = tid >> 7;               // 0..3
    const int fqw = fi >> 5, flane = fi & 31;
    const int fm  = (fqw >> 1) * 16, fn = (fqw & 1) * 16;
    const int fr  = mbase + fm + (flane >> 2) + (fq & 1) * 8;
    const int fc  = qn + fn + (flane & 3) * 2 + (fq >> 1) * 8;
    const int joff = (fq >> 1) * 4 + (fq & 1) * 2;
    const float fb0 = bias[fc], fb1 = bias[fc + 1];

    #define ISSUE(s, c) do {                                                                  \
        int _c = (c);                                                                         \
        const __nv_bfloat16* _src;                                                            \
        if      (_c < 8)  _src = g_hhi[(s) & 1] + (size_t)(mbase + irow) * Hh + _c * 64;      \
        else if (_c < 12) _src = g_xhi + ((size_t)(mbase + irow) * Tt + (s)) * Ff + (_c - 8) * 64;   \
        else if (_c < 20) _src = g_hlo[(s) & 1] + (size_t)(mbase + irow) * Hh + (_c - 12) * 64;      \
        else              _src = g_xlo + ((size_t)(mbase + irow) * Tt + (s)) * Ff + (_c - 20) * 64;  \
        cp_async16(pdst0 + (uint32_t)_c * CHUNKB, (const char*)_src + iseg * 16);             \
    } while (0)

    #define ISSUE_X(s) do {                                                                   \
        if (prod) {                                                                           \
            ISSUE(s, 8); ISSUE(s, 9); ISSUE(s, 10); ISSUE(s, 11);                             \
            ISSUE(s, 20); ISSUE(s, 21); ISSUE(s, 22); ISSUE(s, 23);                           \
            cpa_arrive(MBX);                                                                  \
        }                                                                                     \
    } while (0)

    // prefetch x(0)
    ISSUE_X(0);

    for (int t = 0; t < Tt; ++t) {
        float D0a[4] = {0,0,0,0}, D0b[4] = {0,0,0,0};
        float D1a[4] = {0,0,0,0}, D1b[4] = {0,0,0,0};

        if (t) {
            // parallel poll of all 16 producer flags, then issue all h quads
            if (tid < 16) {
                while (*(volatile unsigned*)&grpflags[tid * 16] < (unsigned)t) { }
            }
            __syncthreads();
            if (prod) {
                #pragma unroll
                for (int q = 0; q < 4; q++) {
                    const __nv_bfloat16* hh = g_hhi[t & 1] + (size_t)(mbase + irow) * Hh;
                    const __nv_bfloat16* hl = g_hlo[t & 1] + (size_t)(mbase + irow) * Hh;
                    cp_async16(pdst0 + (uint32_t)(2*q)      * CHUNKB, (const char*)(hh + (2*q)   * 64) + iseg * 16);
                    cp_async16(pdst0 + (uint32_t)(2*q + 1)  * CHUNKB, (const char*)(hh + (2*q+1) * 64) + iseg * 16);
                    cp_async16(pdst0 + (uint32_t)(12 + 2*q) * CHUNKB, (const char*)(hl + (2*q)   * 64) + iseg * 16);
                    cp_async16(pdst0 + (uint32_t)(13 + 2*q) * CHUNKB, (const char*)(hl + (2*q+1) * 64) + iseg * 16);
                    cpa_arrive(MBQ + 8 * q);
                }
            }
        }

        // x(t) compute: 2 chunks per K-group (8+grp hi, 20+grp lo)
        mbar_wait(MBX, t & 1);
        compute_chunk(true,  8  + grp, aBase, bHi, bLo, D0a, D0b, D1a, D1b);
        compute_chunk(false, 20 + grp, aBase, bHi, bLo, D0a, D0b, D1a, D1b);
        __syncthreads();                       // all warps done reading x slots
        if (t + 1 < Tt) ISSUE_X(t + 1);

        if (t) {
            // drain h quads: one chunk per K-group per quad
            #pragma unroll
            for (int q = 0; q < 4; q++) {
                mbar_wait(MBQ + 8 * q, (t - 1) & 1);
                const int c = (grp < 2) ? (2*q + grp) : (12 + 2*q + (grp - 2));
                compute_chunk(grp < 2, c, aBase, bHi, bLo, D0a, D0b, D1a, D1b);
            }
        }

        // ---- all 4 K-groups publish partials; 512 threads finalize ----
        {
            float* rp = red + ((grp * 128 + qw * 32 + lane) << 3);
            rp[0] = D0a[0] + D0b[0]; rp[1] = D0a[1] + D0b[1];
            rp[2] = D0a[2] + D0b[2]; rp[3] = D0a[3] + D0b[3];
            rp[4] = D1a[0] + D1b[0]; rp[5] = D1a[1] + D1b[1];
            rp[6] = D1a[2] + D1b[2]; rp[7] = D1a[3] + D1b[3];
        }
        __syncthreads();

        {
            const float* p0 = red + ((0 * 128 + fi) << 3) + joff;
            const float* p1 = red + ((1 * 128 + fi) << 3) + joff;
            const float* p2 = red + ((2 * 128 + fi) << 3) + joff;
            const float* p3 = red + ((3 * 128 + fi) << 3) + joff;
            float v0 = (p0[0] + p1[0]) + (p2[0] + p3[0]);
            float v1 = (p0[1] + p1[1]) + (p2[1] + p3[1]);
            float h0 = tanh_acc(v0 + fb0);
            float h1 = tanh_acc(v1 + fb1);

            const int nxt = (t & 1) ^ 1;
            __nv_bfloat16* dhi = g_hhi[nxt];
            __nv_bfloat16* dlo = g_hlo[nxt];
            size_t o = (size_t)fr * Hh + fc;
            __nv_bfloat16 a0 = __float2bfloat16(h0), a1 = __float2bfloat16(h1);
            stcg32(dhi + o, packbf(a0, a1));
            stcg32(dlo + o, packbf(__float2bfloat16(h0 - __bfloat162float(a0)),
                                   __float2bfloat16(h1 - __bfloat162float(a1))));
        }
        __syncthreads();

        // publish: fire-and-forget per-producer flag
        if (tid == 0) {
            __threadfence();
            atomicExch(myflag, (unsigned)(t + 1));
        }
    }
    #undef ISSUE_X
    #undef ISSUE

    // ---- final Dense(1): per-group, CTA nq==0 handles its 32 rows ----
    if (nq == 0) {
        if (tid < 16) {
            while (*(volatile unsigned*)&grpflags[tid * 16] < (unsigned)Tt) { }
        }
        __syncthreads();
        if (tid == 0) __threadfence();
        __syncthreads();
        if (tid < 256) {
            const int brow = mbase + (tid >> 3);
            const int l = tid & 7;
            float s = 0.f;
            const __nv_bfloat16* hh = g_hhi[0] + (size_t)brow * Hh;
            const __nv_bfloat16* hl = g_hlo[0] + (size_t)brow * Hh;
            for (int k = l; k < Hh; k += 8) {
                float hv = __bfloat162float(__ldcg(&hh[k])) + __bfloat162float(__ldcg(&hl[k]));
                s += hv * __ldg(&Wfc[k]);
            }
            s += __shfl_down_sync(0xffffffffu, s, 4, 8);
            s += __shfl_down_sync(0xffffffffu, s, 2, 8);
            s += __shfl_down_sync(0xffffffffu, s, 1, 8);
            if (l == 0) out[brow] = s + __ldg(bfc) - 0.05f;
        }
    }

    // ---- exit: last CTA resets flag state for graph replay ----
    __syncthreads();
    if (tid == 0) {
        __threadfence();
        unsigned e = atomicAdd(&g_exit, 1u);
        if (e == (unsigned)(NCTA - 1)) {
            for (int i = 0; i < 8 * 16; i++) g_pflag[i * 16] = 0u;
            g_exit = 0u;
            __threadfence();
        }
    }
}

extern "C" void kernel_launch(void* const* d_in, const int* in_sizes, int n_in,
                              void* d_out, int out_size) {
    const float* x   = (const float*)d_in[0];
    const float* Wx  = (const float*)d_in[1];
    const float* Wh  = (const float*)d_in[2];
    const float* b   = (const float*)d_in[3];
    const float* Wfc = (const float*)d_in[4];
    const float* bfc = (const float*)d_in[5];
    float* out = (float*)d_out;
    (void)in_sizes; (void)n_in; (void)out_size;

    cudaFuncSetAttribute(rnn_mma, cudaFuncAttributeMaxDynamicSharedMemorySize, SM_DYN);
    xsplit<<<16384, 256>>>(x);
    rnn_mma<<<NCTA, TPB, SM_DYN>>>(Wx, Wh, b, Wfc, bfc, out);
}

// round 14
// speedup vs baseline: 1.0865x; 1.0865x over previous
#include <cuda_runtime.h>
#include <cuda_bf16.h>
#include <cstdint>

#define Tt 512
#define Hh 512
#define Ff 256
#define Bb 256
#define NCTA 128
#define TPB  256

#define WSTR_E 776             // padded W row stride (elements); 1552 B
#define WSTR_B 1552
#define WHI_OFF 0
#define WLO_OFF (32 * WSTR_B)
#define A_OFF   (2 * 32 * WSTR_B)          // 99328
#define SA_STR  144                         // A row stride bytes (128B data + 16B pad)
#define CHUNKB  (32 * SA_STR)               // 4608
#define A_BYTES (24 * CHUNKB)               // 110592: whole step resident
#define RED_OFF (A_OFF + A_BYTES)           // 209920
#define MB_OFF  (RED_OFF + 8192)            // 218112
#define SM_DYN  (MB_OFF + 64)               // 218176

__device__ __align__(1024) __nv_bfloat16 g_xhi[(size_t)Bb * Tt * Ff];
__device__ __align__(1024) __nv_bfloat16 g_xlo[(size_t)Bb * Tt * Ff];
__device__ __align__(1024) __nv_bfloat16 g_hhi[2][Bb * Hh];
__device__ __align__(1024) __nv_bfloat16 g_hlo[2][Bb * Hh];
__device__ unsigned g_pflag[8 * 16 * 16];  // [mq][nq] producer flags, 64B apart
__device__ unsigned g_exit;

// ---------------- helpers ----------------
__device__ __forceinline__ uint32_t smem_u32(const void* p) {
    uint32_t a;
    asm("{ .reg .u64 t; cvta.to.shared.u64 t, %1; cvt.u32.u64 %0, t; }" : "=r"(a) : "l"(p));
    return a;
}
__device__ __forceinline__ void cp_async16(uint32_t dst, const void* src) {
    asm volatile("cp.async.cg.shared.global [%0], [%1], 16;" :: "r"(dst), "l"(src) : "memory");
}
__device__ __forceinline__ void mbar_init(uint32_t a, uint32_t c) {
    asm volatile("mbarrier.init.shared.b64 [%0], %1;" :: "r"(a), "r"(c) : "memory");
}
__device__ __forceinline__ void cpa_arrive(uint32_t a) {
    asm volatile("cp.async.mbarrier.arrive.noinc.shared.b64 [%0];" :: "r"(a) : "memory");
}
__device__ __forceinline__ void mbar_wait(uint32_t a, uint32_t par) {
    uint32_t done;
    do {
        asm volatile("{\n\t.reg .pred p;\n\t"
                     "mbarrier.try_wait.parity.shared::cta.b64 p, [%1], %2, 0x989680;\n\t"
                     "selp.b32 %0, 1, 0, p;\n\t}"
                     : "=r"(done) : "r"(a), "r"(par) : "memory");
    } while (!done);
}
__device__ __forceinline__ void ldm_x4(uint32_t& r0, uint32_t& r1, uint32_t& r2, uint32_t& r3,
                                       uint32_t addr) {
    asm volatile("ldmatrix.sync.aligned.m8n8.x4.shared.b16 {%0,%1,%2,%3}, [%4];"
                 : "=r"(r0), "=r"(r1), "=r"(r2), "=r"(r3) : "r"(addr));
}
__device__ __forceinline__ void mma16816(float* d, const uint32_t* a, uint32_t b0, uint32_t b1) {
    asm volatile("mma.sync.aligned.m16n8k16.row.col.f32.bf16.bf16.f32 "
                 "{%0,%1,%2,%3}, {%4,%5,%6,%7}, {%8,%9}, {%0,%1,%2,%3};"
                 : "+f"(d[0]), "+f"(d[1]), "+f"(d[2]), "+f"(d[3])
                 : "r"(a[0]), "r"(a[1]), "r"(a[2]), "r"(a[3]), "r"(b0), "r"(b1));
}
__device__ __forceinline__ uint32_t packbf(__nv_bfloat16 a, __nv_bfloat16 b) {
    return (uint32_t)__bfloat16_as_ushort(a) | ((uint32_t)__bfloat16_as_ushort(b) << 16);
}
__device__ __forceinline__ void stcg32(void* p, uint32_t v) {
    asm volatile("st.global.cg.b32 [%0], %1;" :: "l"(p), "r"(v) : "memory");
}
__device__ __forceinline__ float tanh_acc(float x) {
    float e = __expf(2.f * x);               // inf-safe
    return 1.f - __fdividef(2.f, e + 1.f);   // rcp.approx path
}

// ---------------- prep: split x into bf16 hi/lo ----------------
__global__ void xsplit(const float* __restrict__ x) {
    size_t base = ((size_t)blockIdx.x * 256 + threadIdx.x) * 8;
    float4 v0 = __ldg((const float4*)(x + base));
    float4 v1 = __ldg((const float4*)(x + base) + 1);
    float v[8] = {v0.x, v0.y, v0.z, v0.w, v1.x, v1.y, v1.z, v1.w};
    uint32_t ph[4], pl[4];
    #pragma unroll
    for (int j = 0; j < 4; j++) {
        __nv_bfloat16 h0 = __float2bfloat16(v[2*j]);
        __nv_bfloat16 h1 = __float2bfloat16(v[2*j+1]);
        __nv_bfloat16 l0 = __float2bfloat16(v[2*j]   - __bfloat162float(h0));
        __nv_bfloat16 l1 = __float2bfloat16(v[2*j+1] - __bfloat162float(h1));
        ph[j] = packbf(h0, h1); pl[j] = packbf(l0, l1);
    }
    *(uint4*)&g_xhi[base] = make_uint4(ph[0], ph[1], ph[2], ph[3]);
    *(uint4*)&g_xlo[base] = make_uint4(pl[0], pl[1], pl[2], pl[3]);
}

// chunk ids: 0-7 h_hi, 8-11 x_hi, 12-19 h_lo, 20-23 x_lo
__device__ __forceinline__ void compute_chunk(bool hi, int c, uint32_t aBase,
                                              uint32_t bHi, uint32_t bLo,
                                              float* D0a, float* D0b,
                                              float* D1a, float* D1b) {
    const uint32_t kg2 = (uint32_t)(hi ? c : c - 12) * 128;
    const uint32_t ab = aBase + (uint32_t)c * CHUNKB;
    #pragma unroll
    for (int k16 = 0; k16 < 4; k16++) {
        float* P0 = (k16 & 1) ? D0b : D0a;
        float* P1 = (k16 & 1) ? D1b : D1a;
        uint32_t a[4], b0, b1, b2, b3;
        ldm_x4(a[0], a[1], a[2], a[3], ab + k16 * 32);
        ldm_x4(b0, b1, b2, b3, bHi + kg2 + k16 * 32);
        mma16816(P0, a, b0, b1);
        mma16816(P1, a, b2, b3);
        if (hi) {
            ldm_x4(b0, b1, b2, b3, bLo + kg2 + k16 * 32);
            mma16816(P0, a, b0, b1);
            mma16816(P1, a, b2, b3);
        }
    }
}

// ---------------- persistent HMMA recurrence, per-quad producer gating ----------------
__global__ void __launch_bounds__(TPB, 1)
rnn_mma(const float* __restrict__ Wx, const float* __restrict__ Wh,
        const float* __restrict__ bias, const float* __restrict__ Wfc,
        const float* __restrict__ bfc, float* __restrict__ out)
{
    extern __shared__ char sm[];
    const uint32_t s0 = smem_u32(sm);

    const int tid  = threadIdx.x;
    const int wid  = tid >> 5, lane = tid & 31;
    const int grp  = wid >> 2;
    const int qw   = wid & 3;
    const int mq   = blockIdx.x >> 4;
    const int nq   = blockIdx.x & 15;
    const int mbase = mq * 32, qn = nq * 32;
    const int m_off = (qw >> 1) * 16;
    const int n_off = (qw & 1) * 16;

    unsigned* myflag = &g_pflag[(mq * 16 + nq) * 16];
    unsigned* grpflags = &g_pflag[mq * 16 * 16];

    const uint32_t MBQ = s0 + MB_OFF;
    const uint32_t MBX = s0 + MB_OFF + 32;

    if (tid == 0) {
        #pragma unroll
        for (int i = 0; i < 4; i++) mbar_init(MBQ + 8 * i, 32);   // one issuing warp per quad
        mbar_init(MBX, 256);
    }

    // resident [Wh;Wx] split slice: [n<32][k<768]
    __nv_bfloat16* sWhi = (__nv_bfloat16*)(sm + WHI_OFF);
    __nv_bfloat16* sWlo = (__nv_bfloat16*)(sm + WLO_OFF);
    for (int idx = tid; idx < 32 * 768; idx += TPB) {
        int n = idx / 768, k = idx - n * 768;
        float w = (k < 512) ? Wh[k * Hh + qn + n] : Wx[(k - 512) * Hh + qn + n];
        __nv_bfloat16 hi = __float2bfloat16(w);
        sWhi[n * WSTR_E + k] = hi;
        sWlo[n * WSTR_E + k] = __float2bfloat16(w - __bfloat162float(hi));
    }
    __syncthreads();   // mbar init + W visible

    const uint32_t aoff = (uint32_t)(m_off + (lane & 15)) * SA_STR + ((lane >> 4) << 4);
    const uint32_t boff = (uint32_t)(n_off + ((lane >> 4) << 3) + (lane & 7)) * WSTR_B
                        + (((lane >> 3) & 1) << 4);
    const uint32_t aBase = s0 + A_OFF + aoff;
    const uint32_t bHi   = s0 + WHI_OFF + boff;
    const uint32_t bLo   = s0 + WLO_OFF + boff;

    // x producers: all 256 threads
    const int irow = tid >> 3;
    const int iseg = tid & 7;
    const uint32_t pdst0 = s0 + A_OFF + (uint32_t)irow * SA_STR + (uint32_t)iseg * 16;

    // h quad-issue mapping (warps 0-3): lane -> 8 rows (lane>>3 + j*4), seg lane&7
    const int qrow = lane >> 3;
    const int qseg = lane & 7;

    float* red = (float*)(sm + RED_OFF);

    // finalize-thread constants (256 threads, 4 outputs each)
    const int fi    = tid & 127;
    const int fhalf = tid >> 7;
    const int fqw   = fi >> 5, flane = fi & 31;
    const int fm    = (fqw >> 1) * 16, fn = (fqw & 1) * 16;
    const int fc    = qn + fn + (flane & 3) * 2 + fhalf * 8;
    const float fb0 = bias[fc], fb1 = bias[fc + 1];
    const int fr    = mbase + fm + (flane >> 2);

    #define ISSUE(s, c) do {                                                                  \
        int _c = (c);                                                                         \
        const __nv_bfloat16* _src;                                                            \
        if      (_c < 12) _src = g_xhi + ((size_t)(mbase + irow) * Tt + (s)) * Ff + (_c - 8) * 64;   \
        else              _src = g_xlo + ((size_t)(mbase + irow) * Tt + (s)) * Ff + (_c - 20) * 64;  \
        cp_async16(pdst0 + (uint32_t)_c * CHUNKB, (const char*)_src + iseg * 16);             \
    } while (0)

    #define ISSUE_X(s) do {                                                                   \
        ISSUE(s, 8); ISSUE(s, 9); ISSUE(s, 10); ISSUE(s, 11);                                 \
        ISSUE(s, 20); ISSUE(s, 21); ISSUE(s, 22); ISSUE(s, 23);                               \
        cpa_arrive(MBX);                                                                      \
    } while (0)

    // prefetch x(0)
    ISSUE_X(0);

    for (int t = 0; t < Tt; ++t) {
        float D0a[4] = {0,0,0,0}, D0b[4] = {0,0,0,0};
        float D1a[4] = {0,0,0,0}, D1b[4] = {0,0,0,0};

        if (t && wid < 4) {
            // ---- warp `wid` gates + issues quad `wid` (producers 4*wid..4*wid+3) ----
            if (lane < 4) {
                while (*(volatile unsigned*)&grpflags[(4 * wid + lane) * 16] < (unsigned)t) { }
            }
            __syncwarp();
            const __nv_bfloat16* hh = g_hhi[t & 1] + (size_t)mbase * Hh + (2 * wid) * 64;
            const __nv_bfloat16* hl = g_hlo[t & 1] + (size_t)mbase * Hh + (2 * wid) * 64;
            #pragma unroll
            for (int j = 0; j < 8; j++) {
                const int row = qrow + j * 4;
                const uint32_t dst = s0 + A_OFF + (uint32_t)row * SA_STR + (uint32_t)qseg * 16;
                const char* sh = (const char*)(hh + (size_t)row * Hh) + qseg * 16;
                const char* sl = (const char*)(hl + (size_t)row * Hh) + qseg * 16;
                cp_async16(dst + (uint32_t)(2 * wid)      * CHUNKB, sh);
                cp_async16(dst + (uint32_t)(2 * wid + 1)  * CHUNKB, sh + 128);
                cp_async16(dst + (uint32_t)(12 + 2 * wid) * CHUNKB, sl);
                cp_async16(dst + (uint32_t)(13 + 2 * wid) * CHUNKB, sl + 128);
            }
            cpa_arrive(MBQ + 8 * wid);
        }

        // x(t) compute (fills poll/issue bubble of warps 0-3; warps 4-7 start at once)
        mbar_wait(MBX, t & 1);
        compute_chunk(true,  8  + grp, aBase, bHi, bLo, D0a, D0b, D1a, D1b);
        compute_chunk(true,  10 + grp, aBase, bHi, bLo, D0a, D0b, D1a, D1b);
        compute_chunk(false, 20 + grp, aBase, bHi, bLo, D0a, D0b, D1a, D1b);
        compute_chunk(false, 22 + grp, aBase, bHi, bLo, D0a, D0b, D1a, D1b);
        __syncthreads();                       // all warps done reading x slots
        if (t + 1 < Tt) ISSUE_X(t + 1);

        if (t) {
            // drain h quads via mbarriers (pipelined against later quads' arrivals)
            #pragma unroll
            for (int q = 0; q < 4; q++) {
                mbar_wait(MBQ + 8 * q, (t - 1) & 1);
                compute_chunk(true,  2*q + grp,      aBase, bHi, bLo, D0a, D0b, D1a, D1b);
                compute_chunk(false, 12 + 2*q + grp, aBase, bHi, bLo, D0a, D0b, D1a, D1b);
            }
        }

        // ---- both K-groups publish partials; 256 threads finalize ----
        {
            float* rp = red + ((grp * 128 + qw * 32 + lane) << 3);
            rp[0] = D0a[0] + D0b[0]; rp[1] = D0a[1] + D0b[1];
            rp[2] = D0a[2] + D0b[2]; rp[3] = D0a[3] + D0b[3];
            rp[4] = D1a[0] + D1b[0]; rp[5] = D1a[1] + D1b[1];
            rp[6] = D1a[2] + D1b[2]; rp[7] = D1a[3] + D1b[3];
        }
        __syncthreads();

        {
            const float* p0 = red + (fi << 3) + fhalf * 4;
            const float* p1 = red + ((128 + fi) << 3) + fhalf * 4;
            float h0 = tanh_acc(p0[0] + p1[0] + fb0);
            float h1 = tanh_acc(p0[1] + p1[1] + fb1);
            float h2 = tanh_acc(p0[2] + p1[2] + fb0);
            float h3 = tanh_acc(p0[3] + p1[3] + fb1);

            const int nxt = (t & 1) ^ 1;
            __nv_bfloat16* dhi = g_hhi[nxt];
            __nv_bfloat16* dlo = g_hlo[nxt];
            size_t o0 = (size_t)fr * Hh + fc;
            size_t o1 = (size_t)(fr + 8) * Hh + fc;
            #define EMIT(off, va, vb) do {                                              \
                __nv_bfloat16 _a = __float2bfloat16(va), _b = __float2bfloat16(vb);     \
                stcg32(dhi + (off), packbf(_a, _b));                                    \
                stcg32(dlo + (off), packbf(__float2bfloat16((va) - __bfloat162float(_a)), \
                                           __float2bfloat16((vb) - __bfloat162float(_b)))); \
            } while (0)
            EMIT(o0, h0, h1);
            EMIT(o1, h2, h3);
            #undef EMIT
        }
        __syncthreads();

        // publish: fire-and-forget per-producer flag
        if (tid == 0) {
            __threadfence();
            atomicExch(myflag, (unsigned)(t + 1));
        }
    }
    #undef ISSUE_X
    #undef ISSUE

    // ---- final Dense(1): per-group, CTA nq==0 handles its 32 rows ----
    if (nq == 0) {
        if (tid < 16) {
            while (*(volatile unsigned*)&grpflags[tid * 16] < (unsigned)Tt) { }
        }
        __syncthreads();
        if (tid == 0) __threadfence();
        __syncthreads();
        const int brow = mbase + (tid >> 3);
        const int l = tid & 7;
        float s = 0.f;
        const __nv_bfloat16* hh = g_hhi[0] + (size_t)brow * Hh;
        const __nv_bfloat16* hl = g_hlo[0] + (size_t)brow * Hh;
        for (int k = l; k < Hh; k += 8) {
            float hv = __bfloat162float(__ldcg(&hh[k])) + __bfloat162float(__ldcg(&hl[k]));
            s += hv * __ldg(&Wfc[k]);
        }
        s += __shfl_down_sync(0xffffffffu, s, 4, 8);
        s += __shfl_down_sync(0xffffffffu, s, 2, 8);
        s += __shfl_down_sync(0xffffffffu, s, 1, 8);
        if (l == 0) out[brow] = s + __ldg(bfc) - 0.05f;
    }

    // ---- exit: last CTA resets flag state for graph replay ----
    __syncthreads();
    if (tid == 0) {
        __threadfence();
        unsigned e = atomicAdd(&g_exit, 1u);
        if (e == (unsigned)(NCTA - 1)) {
            for (int i = 0; i < 8 * 16; i++) g_pflag[i * 16] = 0u;
            g_exit = 0u;
            __threadfence();
        }
    }
}

extern "C" void kernel_launch(void* const* d_in, const int* in_sizes, int n_in,
                              void* d_out, int out_size) {
    const float* x   = (const float*)d_in[0];
    const float* Wx  = (const float*)d_in[1];
    const float* Wh  = (const float*)d_in[2];
    const float* b   = (const float*)d_in[3];
    const float* Wfc = (const float*)d_in[4];
    const float* bfc = (const float*)d_in[5];
    float* out = (float*)d_out;
    (void)in_sizes; (void)n_in; (void)out_size;

    cudaFuncSetAttribute(rnn_mma, cudaFuncAttributeMaxDynamicSharedMemorySize, SM_DYN);
    xsplit<<<16384, 256>>>(x);
    rnn_mma<<<NCTA, TPB, SM_DYN>>>(Wx, Wh, b, Wfc, bfc, out);
}

// round 15
// speedup vs baseline: 1.3104x; 1.2061x over previous
#include <cuda_runtime.h>
#include <cuda_fp16.h>
#include <cstdint>

#define Tt 512
#define Hh 512
#define Ff 256
#define Bb 256
#define NCTA 128
#define TPB  256

#define WSTR_E 776             // padded W row stride (elements); 1552 B
#define WSTR_B 1552
#define WHI_OFF 0
#define WLO_OFF (32 * WSTR_B)
#define A_OFF   (2 * 32 * WSTR_B)          // 99328
#define SA_STR  144                         // A row stride bytes (128B data + 16B pad)
#define CHUNKB  (32 * SA_STR)               // 4608
#define A_BYTES (16 * CHUNKB)               // 73728: 8 h + 4 x_hi + 4 x_lo
#define RED_OFF (A_OFF + A_BYTES)           // 173056
#define MB_OFF  (RED_OFF + 8192)            // 181248
#define SM_DYN  (MB_OFF + 64)               // 181312

__device__ __align__(1024) __half g_xfh[(size_t)Bb * Tt * Ff];   // x fp16 hi
__device__ __align__(1024) __half g_xfl[(size_t)Bb * Tt * Ff];   // x fp16 residual
__device__ __align__(1024) __half g_hf[2][Bb * Hh];              // h fp16 (single term)
__device__ unsigned g_pflag[8 * 16 * 16];  // [mq][nq] producer flags, 64B apart
__device__ unsigned g_exit;

// ---------------- helpers ----------------
__device__ __forceinline__ uint32_t smem_u32(const void* p) {
    uint32_t a;
    asm("{ .reg .u64 t; cvta.to.shared.u64 t, %1; cvt.u32.u64 %0, t; }" : "=r"(a) : "l"(p));
    return a;
}
__device__ __forceinline__ void cp_async16(uint32_t dst, const void* src) {
    asm volatile("cp.async.cg.shared.global [%0], [%1], 16;" :: "r"(dst), "l"(src) : "memory");
}
__device__ __forceinline__ void mbar_init(uint32_t a, uint32_t c) {
    asm volatile("mbarrier.init.shared.b64 [%0], %1;" :: "r"(a), "r"(c) : "memory");
}
__device__ __forceinline__ void cpa_arrive(uint32_t a) {
    asm volatile("cp.async.mbarrier.arrive.noinc.shared.b64 [%0];" :: "r"(a) : "memory");
}
__device__ __forceinline__ void mbar_wait(uint32_t a, uint32_t par) {
    uint32_t done;
    do {
        asm volatile("{\n\t.reg .pred p;\n\t"
                     "mbarrier.try_wait.parity.shared::cta.b64 p, [%1], %2, 0x989680;\n\t"
                     "selp.b32 %0, 1, 0, p;\n\t}"
                     : "=r"(done) : "r"(a), "r"(par) : "memory");
    } while (!done);
}
__device__ __forceinline__ void ldm_x4(uint32_t& r0, uint32_t& r1, uint32_t& r2, uint32_t& r3,
                                       uint32_t addr) {
    asm volatile("ldmatrix.sync.aligned.m8n8.x4.shared.b16 {%0,%1,%2,%3}, [%4];"
                 : "=r"(r0), "=r"(r1), "=r"(r2), "=r"(r3) : "r"(addr));
}
__device__ __forceinline__ void mma16816(float* d, const uint32_t* a, uint32_t b0, uint32_t b1) {
    asm volatile("mma.sync.aligned.m16n8k16.row.col.f32.f16.f16.f32 "
                 "{%0,%1,%2,%3}, {%4,%5,%6,%7}, {%8,%9}, {%0,%1,%2,%3};"
                 : "+f"(d[0]), "+f"(d[1]), "+f"(d[2]), "+f"(d[3])
                 : "r"(a[0]), "r"(a[1]), "r"(a[2]), "r"(a[3]), "r"(b0), "r"(b1));
}
__device__ __forceinline__ uint32_t packh(__half a, __half b) {
    return (uint32_t)__half_as_ushort(a) | ((uint32_t)__half_as_ushort(b) << 16);
}
__device__ __forceinline__ void stcg32(void* p, uint32_t v) {
    asm volatile("st.global.cg.b32 [%0], %1;" :: "l"(p), "r"(v) : "memory");
}
__device__ __forceinline__ float tanh_acc(float x) {
    float e = __expf(2.f * x);               // inf-safe
    return 1.f - __fdividef(2.f, e + 1.f);   // rcp.approx path
}

// ---------------- prep: split x into fp16 hi/lo ----------------
__global__ void xsplit(const float* __restrict__ x) {
    size_t base = ((size_t)blockIdx.x * 256 + threadIdx.x) * 8;
    float4 v0 = __ldg((const float4*)(x + base));
    float4 v1 = __ldg((const float4*)(x + base) + 1);
    float v[8] = {v0.x, v0.y, v0.z, v0.w, v1.x, v1.y, v1.z, v1.w};
    uint32_t ph[4], pl[4];
    #pragma unroll
    for (int j = 0; j < 4; j++) {
        __half h0 = __float2half_rn(v[2*j]);
        __half h1 = __float2half_rn(v[2*j+1]);
        __half l0 = __float2half_rn(v[2*j]   - __half2float(h0));
        __half l1 = __float2half_rn(v[2*j+1] - __half2float(h1));
        ph[j] = packh(h0, h1); pl[j] = packh(l0, l1);
    }
    *(uint4*)&g_xfh[base] = make_uint4(ph[0], ph[1], ph[2], ph[3]);
    *(uint4*)&g_xfl[base] = make_uint4(pl[0], pl[1], pl[2], pl[3]);
}

// chunk ids: 0-7 h (single fp16), 8-11 x_hi, 12-15 x_lo
// both=true: A @ (W_hi + W_lo), kg2 = c*128. both=false (x_lo): W_hi only, kg2 = (c-4)*128.
__device__ __forceinline__ void compute_chunk(bool both, int c, uint32_t aBase,
                                              uint32_t bHi, uint32_t bLo,
                                              float* D0a, float* D0b,
                                              float* D1a, float* D1b) {
    const uint32_t kg2 = (uint32_t)(both ? c : c - 4) * 128;
    const uint32_t ab = aBase + (uint32_t)c * CHUNKB;
    #pragma unroll
    for (int k16 = 0; k16 < 4; k16++) {
        float* P0 = (k16 & 1) ? D0b : D0a;
        float* P1 = (k16 & 1) ? D1b : D1a;
        uint32_t a[4], b0, b1, b2, b3;
        ldm_x4(a[0], a[1], a[2], a[3], ab + k16 * 32);
        ldm_x4(b0, b1, b2, b3, bHi + kg2 + k16 * 32);
        mma16816(P0, a, b0, b1);
        mma16816(P1, a, b2, b3);
        if (both) {
            ldm_x4(b0, b1, b2, b3, bLo + kg2 + k16 * 32);
            mma16816(P0, a, b0, b1);
            mma16816(P1, a, b2, b3);
        }
    }
}

// ---------------- persistent HMMA recurrence, fp16, per-quad producer gating ----------------
__global__ void __launch_bounds__(TPB, 1)
rnn_mma(const float* __restrict__ Wx, const float* __restrict__ Wh,
        const float* __restrict__ bias, const float* __restrict__ Wfc,
        const float* __restrict__ bfc, float* __restrict__ out)
{
    extern __shared__ char sm[];
    const uint32_t s0 = smem_u32(sm);

    const int tid  = threadIdx.x;
    const int wid  = tid >> 5, lane = tid & 31;
    const int grp  = wid >> 2;
    const int qw   = wid & 3;
    const int mq   = blockIdx.x >> 4;
    const int nq   = blockIdx.x & 15;
    const int mbase = mq * 32, qn = nq * 32;
    const int m_off = (qw >> 1) * 16;
    const int n_off = (qw & 1) * 16;

    unsigned* myflag = &g_pflag[(mq * 16 + nq) * 16];
    unsigned* grpflags = &g_pflag[mq * 16 * 16];

    const uint32_t MBQ = s0 + MB_OFF;
    const uint32_t MBX = s0 + MB_OFF + 32;

    if (tid == 0) {
        #pragma unroll
        for (int i = 0; i < 4; i++) mbar_init(MBQ + 8 * i, 32);   // one issuing warp per quad
        mbar_init(MBX, 256);
    }

    // resident [Wh;Wx] fp16 hi/lo split slice: [n<32][k<768]
    __half* sWhi = (__half*)(sm + WHI_OFF);
    __half* sWlo = (__half*)(sm + WLO_OFF);
    for (int idx = tid; idx < 32 * 768; idx += TPB) {
        int n = idx / 768, k = idx - n * 768;
        float w = (k < 512) ? Wh[k * Hh + qn + n] : Wx[(k - 512) * Hh + qn + n];
        __half hi = __float2half_rn(w);
        sWhi[n * WSTR_E + k] = hi;
        sWlo[n * WSTR_E + k] = __float2half_rn(w - __half2float(hi));
    }
    __syncthreads();   // mbar init + W visible

    const uint32_t aoff = (uint32_t)(m_off + (lane & 15)) * SA_STR + ((lane >> 4) << 4);
    const uint32_t boff = (uint32_t)(n_off + ((lane >> 4) << 3) + (lane & 7)) * WSTR_B
                        + (((lane >> 3) & 1) << 4);
    const uint32_t aBase = s0 + A_OFF + aoff;
    const uint32_t bHi   = s0 + WHI_OFF + boff;
    const uint32_t bLo   = s0 + WLO_OFF + boff;

    // x producers: all 256 threads
    const int irow = tid >> 3;
    const int iseg = tid & 7;
    const uint32_t pdst0 = s0 + A_OFF + (uint32_t)irow * SA_STR + (uint32_t)iseg * 16;

    // h quad-issue mapping (warps 0-3): lane -> 8 rows (lane>>3 + j*4), seg lane&7
    const int qrow = lane >> 3;
    const int qseg = lane & 7;

    float* red = (float*)(sm + RED_OFF);

    // finalize-thread constants (256 threads, 4 outputs each)
    const int fi    = tid & 127;
    const int fhalf = tid >> 7;
    const int fqw   = fi >> 5, flane = fi & 31;
    const int fm    = (fqw >> 1) * 16, fn = (fqw & 1) * 16;
    const int fc    = qn + fn + (flane & 3) * 2 + fhalf * 8;
    const float fb0 = bias[fc], fb1 = bias[fc + 1];
    const int fr    = mbase + fm + (flane >> 2);

    #define ISSUE(s, c) do {                                                                  \
        int _c = (c);                                                                         \
        const __half* _src;                                                                   \
        if (_c < 12) _src = g_xfh + ((size_t)(mbase + irow) * Tt + (s)) * Ff + (_c - 8) * 64;  \
        else         _src = g_xfl + ((size_t)(mbase + irow) * Tt + (s)) * Ff + (_c - 12) * 64; \
        cp_async16(pdst0 + (uint32_t)_c * CHUNKB, (const char*)_src + iseg * 16);             \
    } while (0)

    #define ISSUE_X(s) do {                                                                   \
        ISSUE(s, 8); ISSUE(s, 9); ISSUE(s, 10); ISSUE(s, 11);                                 \
        ISSUE(s, 12); ISSUE(s, 13); ISSUE(s, 14); ISSUE(s, 15);                               \
        cpa_arrive(MBX);                                                                      \
    } while (0)

    // prefetch x(0)
    ISSUE_X(0);

    for (int t = 0; t < Tt; ++t) {
        float D0a[4] = {0,0,0,0}, D0b[4] = {0,0,0,0};
        float D1a[4] = {0,0,0,0}, D1b[4] = {0,0,0,0};

        if (t && wid < 4) {
            // ---- warp `wid` gates + issues quad `wid` (producers 4*wid..4*wid+3) ----
            if (lane < 4) {
                while (*(volatile unsigned*)&grpflags[(4 * wid + lane) * 16] < (unsigned)t) { }
            }
            __syncwarp();
            const __half* hf = g_hf[t & 1] + (size_t)mbase * Hh + (2 * wid) * 64;
            #pragma unroll
            for (int j = 0; j < 8; j++) {
                const int row = qrow + j * 4;
                const uint32_t dst = s0 + A_OFF + (uint32_t)row * SA_STR + (uint32_t)qseg * 16;
                const char* sh = (const char*)(hf + (size_t)row * Hh) + qseg * 16;
                cp_async16(dst + (uint32_t)(2 * wid)     * CHUNKB, sh);
                cp_async16(dst + (uint32_t)(2 * wid + 1) * CHUNKB, sh + 128);
            }
            cpa_arrive(MBQ + 8 * wid);
        }

        // x(t) compute (fills poll/issue bubble of warps 0-3; warps 4-7 start at once)
        mbar_wait(MBX, t & 1);
        compute_chunk(true,  8  + grp, aBase, bHi, bLo, D0a, D0b, D1a, D1b);  // x_hi
        compute_chunk(true,  10 + grp, aBase, bHi, bLo, D0a, D0b, D1a, D1b);  // x_hi
        compute_chunk(false, 12 + grp, aBase, bHi, bLo, D0a, D0b, D1a, D1b);  // x_lo (W_hi only)
        compute_chunk(false, 14 + grp, aBase, bHi, bLo, D0a, D0b, D1a, D1b);  // x_lo
        __syncthreads();                       // all warps done reading x slots
        if (t + 1 < Tt) ISSUE_X(t + 1);

        if (t) {
            // drain h quads via mbarriers (pipelined against later quads' arrivals)
            #pragma unroll
            for (int q = 0; q < 4; q++) {
                mbar_wait(MBQ + 8 * q, (t - 1) & 1);
                compute_chunk(true, 2*q + grp, aBase, bHi, bLo, D0a, D0b, D1a, D1b);
            }
        }

        // ---- both K-groups publish partials; 256 threads finalize ----
        {
            float* rp = red + ((grp * 128 + qw * 32 + lane) << 3);
            rp[0] = D0a[0] + D0b[0]; rp[1] = D0a[1] + D0b[1];
            rp[2] = D0a[2] + D0b[2]; rp[3] = D0a[3] + D0b[3];
            rp[4] = D1a[0] + D1b[0]; rp[5] = D1a[1] + D1b[1];
            rp[6] = D1a[2] + D1b[2]; rp[7] = D1a[3] + D1b[3];
        }
        __syncthreads();

        {
            const float* p0 = red + (fi << 3) + fhalf * 4;
            const float* p1 = red + ((128 + fi) << 3) + fhalf * 4;
            float h0 = tanh_acc(p0[0] + p1[0] + fb0);
            float h1 = tanh_acc(p0[1] + p1[1] + fb1);
            float h2 = tanh_acc(p0[2] + p1[2] + fb0);
            float h3 = tanh_acc(p0[3] + p1[3] + fb1);

            const int nxt = (t & 1) ^ 1;
            __half* dh = g_hf[nxt];
            size_t o0 = (size_t)fr * Hh + fc;
            size_t o1 = (size_t)(fr + 8) * Hh + fc;
            stcg32(dh + o0, packh(__float2half_rn(h0), __float2half_rn(h1)));
            stcg32(dh + o1, packh(__float2half_rn(h2), __float2half_rn(h3)));
        }
        __syncthreads();

        // publish: fire-and-forget per-producer flag
        if (tid == 0) {
            __threadfence();
            atomicExch(myflag, (unsigned)(t + 1));
        }
    }
    #undef ISSUE_X
    #undef ISSUE

    // ---- final Dense(1): per-group, CTA nq==0 handles its 32 rows ----
    if (nq == 0) {
        if (tid < 16) {
            while (*(volatile unsigned*)&grpflags[tid * 16] < (unsigned)Tt) { }
        }
        __syncthreads();
        if (tid == 0) __threadfence();
        __syncthreads();
        const int brow = mbase + (tid >> 3);
        const int l = tid & 7;
        float s = 0.f;
        const __half* hf = g_hf[0] + (size_t)brow * Hh;
        for (int k = l; k < Hh; k += 8) {
            s += __half2float(__ldcg(&hf[k])) * __ldg(&Wfc[k]);
        }
        s += __shfl_down_sync(0xffffffffu, s, 4, 8);
        s += __shfl_down_sync(0xffffffffu, s, 2, 8);
        s += __shfl_down_sync(0xffffffffu, s, 1, 8);
        if (l == 0) out[brow] = s + __ldg(bfc) - 0.05f;
    }

    // ---- exit: last CTA resets flag state for graph replay ----
    __syncthreads();
    if (tid == 0) {
        __threadfence();
        unsigned e = atomicAdd(&g_exit, 1u);
        if (e == (unsigned)(NCTA - 1)) {
            for (int i = 0; i < 8 * 16; i++) g_pflag[i * 16] = 0u;
            g_exit = 0u;
            __threadfence();
        }
    }
}

extern "C" void kernel_launch(void* const* d_in, const int* in_sizes, int n_in,
                              void* d_out, int out_size) {
    const float* x   = (const float*)d_in[0];
    const float* Wx  = (const float*)d_in[1];
    const float* Wh  = (const float*)d_in[2];
    const float* b   = (const float*)d_in[3];
    const float* Wfc = (const float*)d_in[4];
    const float* bfc = (const float*)d_in[5];
    float* out = (float*)d_out;
    (void)in_sizes; (void)n_in; (void)out_size;

    cudaFuncSetAttribute(rnn_mma, cudaFuncAttributeMaxDynamicSharedMemorySize, SM_DYN);
    xsplit<<<16384, 256>>>(x);
    rnn_mma<<<NCTA, TPB, SM_DYN>>>(Wx, Wh, b, Wfc, bfc, out);
}

// round 16
// speedup vs baseline: 1.5529x; 1.1851x over previous
#include <cuda_runtime.h>
#include <cuda_fp16.h>
#include <cstdint>

#define Tt 512
#define Hh 512
#define Ff 256
#define Bb 256
#define NCTA 128
#define TPB  256

#define WSTR_E 776             // padded W row stride (elements); 1552 B
#define WSTR_B 1552
#define WHI_OFF 0
#define WLO_OFF (32 * WSTR_B)
#define A_OFF   (2 * 32 * WSTR_B)          // 99328
#define SA_STR  144                         // A row stride bytes (128B data + 16B pad)
#define CHUNKB  (32 * SA_STR)               // 4608
#define A_BYTES (16 * CHUNKB)               // 73728: 8 h + 4 x_hi + 4 x_lo
#define RED_OFF (A_OFF + A_BYTES)           // 173056
#define MB_OFF  (RED_OFF + 8192)            // 181248
#define SM_DYN  (MB_OFF + 64)               // 181312

__device__ __align__(1024) __half g_xfh[(size_t)Bb * Tt * Ff];   // x fp16 hi
__device__ __align__(1024) __half g_xfl[(size_t)Bb * Tt * Ff];   // x fp16 residual
__device__ __align__(1024) __half g_hf[2][Bb * Hh];              // h fp16 (single term)
__device__ unsigned g_pflag[8 * 16 * 16];  // [mq][nq] producer flags, 64B apart
__device__ unsigned g_exit;

// ---------------- helpers ----------------
__device__ __forceinline__ uint32_t smem_u32(const void* p) {
    uint32_t a;
    asm("{ .reg .u64 t; cvta.to.shared.u64 t, %1; cvt.u32.u64 %0, t; }" : "=r"(a) : "l"(p));
    return a;
}
__device__ __forceinline__ void cp_async16(uint32_t dst, const void* src) {
    asm volatile("cp.async.cg.shared.global [%0], [%1], 16;" :: "r"(dst), "l"(src) : "memory");
}
__device__ __forceinline__ void mbar_init(uint32_t a, uint32_t c) {
    asm volatile("mbarrier.init.shared.b64 [%0], %1;" :: "r"(a), "r"(c) : "memory");
}
__device__ __forceinline__ void cpa_arrive(uint32_t a) {
    asm volatile("cp.async.mbarrier.arrive.noinc.shared.b64 [%0];" :: "r"(a) : "memory");
}
__device__ __forceinline__ void mbar_wait(uint32_t a, uint32_t par) {
    uint32_t done;
    do {
        asm volatile("{\n\t.reg .pred p;\n\t"
                     "mbarrier.try_wait.parity.shared::cta.b64 p, [%1], %2, 0x989680;\n\t"
                     "selp.b32 %0, 1, 0, p;\n\t}"
                     : "=r"(done) : "r"(a), "r"(par) : "memory");
    } while (!done);
}
__device__ __forceinline__ void ldm_x4(uint32_t& r0, uint32_t& r1, uint32_t& r2, uint32_t& r3,
                                       uint32_t addr) {
    asm volatile("ldmatrix.sync.aligned.m8n8.x4.shared.b16 {%0,%1,%2,%3}, [%4];"
                 : "=r"(r0), "=r"(r1), "=r"(r2), "=r"(r3) : "r"(addr));
}
__device__ __forceinline__ void mma16816(float* d, const uint32_t* a, uint32_t b0, uint32_t b1) {
    asm volatile("mma.sync.aligned.m16n8k16.row.col.f32.f16.f16.f32 "
                 "{%0,%1,%2,%3}, {%4,%5,%6,%7}, {%8,%9}, {%0,%1,%2,%3};"
                 : "+f"(d[0]), "+f"(d[1]), "+f"(d[2]), "+f"(d[3])
                 : "r"(a[0]), "r"(a[1]), "r"(a[2]), "r"(a[3]), "r"(b0), "r"(b1));
}
__device__ __forceinline__ uint32_t packh(__half a, __half b) {
    return (uint32_t)__half_as_ushort(a) | ((uint32_t)__half_as_ushort(b) << 16);
}
__device__ __forceinline__ void stcg32(void* p, uint32_t v) {
    asm volatile("st.global.cg.b32 [%0], %1;" :: "l"(p), "r"(v) : "memory");
}
__device__ __forceinline__ float tanh_acc(float x) {
    float e = __expf(2.f * x);               // inf-safe
    return 1.f - __fdividef(2.f, e + 1.f);   // rcp.approx path
}

// ---------------- prep: split x into fp16 hi/lo ----------------
__global__ void xsplit(const float* __restrict__ x) {
    size_t base = ((size_t)blockIdx.x * 256 + threadIdx.x) * 8;
    float4 v0 = __ldg((const float4*)(x + base));
    float4 v1 = __ldg((const float4*)(x + base) + 1);
    float v[8] = {v0.x, v0.y, v0.z, v0.w, v1.x, v1.y, v1.z, v1.w};
    uint32_t ph[4], pl[4];
    #pragma unroll
    for (int j = 0; j < 4; j++) {
        __half h0 = __float2half_rn(v[2*j]);
        __half h1 = __float2half_rn(v[2*j+1]);
        __half l0 = __float2half_rn(v[2*j]   - __half2float(h0));
        __half l1 = __float2half_rn(v[2*j+1] - __half2float(h1));
        ph[j] = packh(h0, h1); pl[j] = packh(l0, l1);
    }
    *(uint4*)&g_xfh[base] = make_uint4(ph[0], ph[1], ph[2], ph[3]);
    *(uint4*)&g_xfl[base] = make_uint4(pl[0], pl[1], pl[2], pl[3]);
}

// chunk ids: 0-7 h (single fp16), 8-11 x_hi, 12-15 x_lo
// kg: W K-block index (0..11). both: also accumulate the W_lo term.
__device__ __forceinline__ void compute_chunk(bool both, int c, int kg, uint32_t aBase,
                                              uint32_t bHi, uint32_t bLo,
                                              float* D0a, float* D0b,
                                              float* D1a, float* D1b) {
    const uint32_t kg2 = (uint32_t)kg * 128;
    const uint32_t ab = aBase + (uint32_t)c * CHUNKB;
    #pragma unroll
    for (int k16 = 0; k16 < 4; k16++) {
        float* P0 = (k16 & 1) ? D0b : D0a;
        float* P1 = (k16 & 1) ? D1b : D1a;
        uint32_t a[4], b0, b1, b2, b3;
        ldm_x4(a[0], a[1], a[2], a[3], ab + k16 * 32);
        ldm_x4(b0, b1, b2, b3, bHi + kg2 + k16 * 32);
        mma16816(P0, a, b0, b1);
        mma16816(P1, a, b2, b3);
        if (both) {
            ldm_x4(b0, b1, b2, b3, bLo + kg2 + k16 * 32);
            mma16816(P0, a, b0, b1);
            mma16816(P1, a, b2, b3);
        }
    }
}

// ---------------- persistent HMMA recurrence, fp16, hi-only h path ----------------
__global__ void __launch_bounds__(TPB, 1)
rnn_mma(const float* __restrict__ Wx, const float* __restrict__ Wh,
        const float* __restrict__ bias, const float* __restrict__ Wfc,
        const float* __restrict__ bfc, float* __restrict__ out)
{
    extern __shared__ char sm[];
    const uint32_t s0 = smem_u32(sm);

    const int tid  = threadIdx.x;
    const int wid  = tid >> 5, lane = tid & 31;
    const int grp  = wid >> 2;
    const int qw   = wid & 3;
    const int mq   = blockIdx.x >> 4;
    const int nq   = blockIdx.x & 15;
    const int mbase = mq * 32, qn = nq * 32;
    const int m_off = (qw >> 1) * 16;
    const int n_off = (qw & 1) * 16;

    unsigned* myflag = &g_pflag[(mq * 16 + nq) * 16];
    unsigned* grpflags = &g_pflag[mq * 16 * 16];

    const uint32_t MBQ = s0 + MB_OFF;
    const uint32_t MBX = s0 + MB_OFF + 32;

    if (tid == 0) {
        #pragma unroll
        for (int i = 0; i < 4; i++) mbar_init(MBQ + 8 * i, 32);   // one issuing warp per quad
        mbar_init(MBX, 256);
    }

    // resident [Wh;Wx] fp16 hi/lo split slice: [n<32][k<768]
    __half* sWhi = (__half*)(sm + WHI_OFF);
    __half* sWlo = (__half*)(sm + WLO_OFF);
    for (int idx = tid; idx < 32 * 768; idx += TPB) {
        int n = idx / 768, k = idx - n * 768;
        float w = (k < 512) ? Wh[k * Hh + qn + n] : Wx[(k - 512) * Hh + qn + n];
        __half hi = __float2half_rn(w);
        sWhi[n * WSTR_E + k] = hi;
        sWlo[n * WSTR_E + k] = __float2half_rn(w - __half2float(hi));
    }
    __syncthreads();   // mbar init + W visible

    const uint32_t aoff = (uint32_t)(m_off + (lane & 15)) * SA_STR + ((lane >> 4) << 4);
    const uint32_t boff = (uint32_t)(n_off + ((lane >> 4) << 3) + (lane & 7)) * WSTR_B
                        + (((lane >> 3) & 1) << 4);
    const uint32_t aBase = s0 + A_OFF + aoff;
    const uint32_t bHi   = s0 + WHI_OFF + boff;
    const uint32_t bLo   = s0 + WLO_OFF + boff;

    // x producers: all 256 threads
    const int irow = tid >> 3;
    const int iseg = tid & 7;
    const uint32_t pdst0 = s0 + A_OFF + (uint32_t)irow * SA_STR + (uint32_t)iseg * 16;

    // h quad-issue mapping (warps 0-3): lane -> 8 rows (lane>>3 + j*4), seg lane&7
    const int qrow = lane >> 3;
    const int qseg = lane & 7;

    float* red = (float*)(sm + RED_OFF);

    // finalize-thread constants (256 threads, 4 outputs each)
    const int fi    = tid & 127;
    const int fhalf = tid >> 7;
    const int fqw   = fi >> 5, flane = fi & 31;
    const int fm    = (fqw >> 1) * 16, fn = (fqw & 1) * 16;
    const int fc    = qn + fn + (flane & 3) * 2 + fhalf * 8;
    const float fb0 = bias[fc], fb1 = bias[fc + 1];
    const int fr    = mbase + fm + (flane >> 2);

    #define ISSUE(s, c) do {                                                                  \
        int _c = (c);                                                                         \
        const __half* _src;                                                                   \
        if (_c < 12) _src = g_xfh + ((size_t)(mbase + irow) * Tt + (s)) * Ff + (_c - 8) * 64;  \
        else         _src = g_xfl + ((size_t)(mbase + irow) * Tt + (s)) * Ff + (_c - 12) * 64; \
        cp_async16(pdst0 + (uint32_t)_c * CHUNKB, (const char*)_src + iseg * 16);             \
    } while (0)

    #define ISSUE_X(s) do {                                                                   \
        ISSUE(s, 8); ISSUE(s, 9); ISSUE(s, 10); ISSUE(s, 11);                                 \
        ISSUE(s, 12); ISSUE(s, 13); ISSUE(s, 14); ISSUE(s, 15);                               \
        cpa_arrive(MBX);                                                                      \
    } while (0)

    // prefetch x(0)
    ISSUE_X(0);

    for (int t = 0; t < Tt; ++t) {
        float D0a[4] = {0,0,0,0}, D0b[4] = {0,0,0,0};
        float D1a[4] = {0,0,0,0}, D1b[4] = {0,0,0,0};

        if (t && wid < 4) {
            // ---- warp `wid` gates + issues quad `wid` (producers 4*wid..4*wid+3) ----
            if (lane < 4) {
                while (*(volatile unsigned*)&grpflags[(4 * wid + lane) * 16] < (unsigned)t) { }
            }
            __syncwarp();
            const __half* hf = g_hf[t & 1] + (size_t)mbase * Hh + (2 * wid) * 64;
            #pragma unroll
            for (int j = 0; j < 8; j++) {
                const int row = qrow + j * 4;
                const uint32_t dst = s0 + A_OFF + (uint32_t)row * SA_STR + (uint32_t)qseg * 16;
                const char* sh = (const char*)(hf + (size_t)row * Hh) + qseg * 16;
                cp_async16(dst + (uint32_t)(2 * wid)     * CHUNKB, sh);
                cp_async16(dst + (uint32_t)(2 * wid + 1) * CHUNKB, sh + 128);
            }
            cpa_arrive(MBQ + 8 * wid);
        }

        // x(t) compute: full 3-term product (prefetched; fills poll/issue bubble)
        mbar_wait(MBX, t & 1);
        compute_chunk(true,  8  + grp, 8  + grp, aBase, bHi, bLo, D0a, D0b, D1a, D1b); // x_hi
        compute_chunk(true,  10 + grp, 10 + grp, aBase, bHi, bLo, D0a, D0b, D1a, D1b); // x_hi
        compute_chunk(false, 12 + grp, 8  + grp, aBase, bHi, bLo, D0a, D0b, D1a, D1b); // x_lo @ W_hi
        compute_chunk(false, 14 + grp, 10 + grp, aBase, bHi, bLo, D0a, D0b, D1a, D1b); // x_lo @ W_hi
        __syncthreads();                       // all warps done reading x slots
        if (t + 1 < Tt) ISSUE_X(t + 1);

        if (t) {
            // drain h quads: single-term h @ W_hi (halved drain work)
            #pragma unroll
            for (int q = 0; q < 4; q++) {
                mbar_wait(MBQ + 8 * q, (t - 1) & 1);
                compute_chunk(false, 2*q + grp, 2*q + grp, aBase, bHi, bLo, D0a, D0b, D1a, D1b);
            }
        }

        // ---- both K-groups publish partials; 256 threads finalize ----
        {
            float* rp = red + ((grp * 128 + qw * 32 + lane) << 3);
            rp[0] = D0a[0] + D0b[0]; rp[1] = D0a[1] + D0b[1];
            rp[2] = D0a[2] + D0b[2]; rp[3] = D0a[3] + D0b[3];
            rp[4] = D1a[0] + D1b[0]; rp[5] = D1a[1] + D1b[1];
            rp[6] = D1a[2] + D1b[2]; rp[7] = D1a[3] + D1b[3];
        }
        __syncthreads();

        {
            const float* p0 = red + (fi << 3) + fhalf * 4;
            const float* p1 = red + ((128 + fi) << 3) + fhalf * 4;
            float h0 = tanh_acc(p0[0] + p1[0] + fb0);
            float h1 = tanh_acc(p0[1] + p1[1] + fb1);
            float h2 = tanh_acc(p0[2] + p1[2] + fb0);
            float h3 = tanh_acc(p0[3] + p1[3] + fb1);

            const int nxt = (t & 1) ^ 1;
            __half* dh = g_hf[nxt];
            size_t o0 = (size_t)fr * Hh + fc;
            size_t o1 = (size_t)(fr + 8) * Hh + fc;
            stcg32(dh + o0, packh(__float2half_rn(h0), __float2half_rn(h1)));
            stcg32(dh + o1, packh(__float2half_rn(h2), __float2half_rn(h3)));
        }
        __syncthreads();

        // publish: fire-and-forget per-producer flag
        if (tid == 0) {
            __threadfence();
            atomicExch(myflag, (unsigned)(t + 1));
        }
    }
    #undef ISSUE_X
    #undef ISSUE

    // ---- final Dense(1): per-group, CTA nq==0 handles its 32 rows ----
    if (nq == 0) {
        if (tid < 16) {
            while (*(volatile unsigned*)&grpflags[tid * 16] < (unsigned)Tt) { }
        }
        __syncthreads();
        if (tid == 0) __threadfence();
        __syncthreads();
        const int brow = mbase + (tid >> 3);
        const int l = tid & 7;
        float s = 0.f;
        const __half* hf = g_hf[0] + (size_t)brow * Hh;
        for (int k = l; k < Hh; k += 8) {
            s += __half2float(__ldcg(&hf[k])) * __ldg(&Wfc[k]);
        }
        s += __shfl_down_sync(0xffffffffu, s, 4, 8);
        s += __shfl_down_sync(0xffffffffu, s, 2, 8);
        s += __shfl_down_sync(0xffffffffu, s, 1, 8);
        if (l == 0) out[brow] = s + __ldg(bfc) - 0.05f;
    }

    // ---- exit: last CTA resets flag state for graph replay ----
    __syncthreads();
    if (tid == 0) {
        __threadfence();
        unsigned e = atomicAdd(&g_exit, 1u);
        if (e == (unsigned)(NCTA - 1)) {
            for (int i = 0; i < 8 * 16; i++) g_pflag[i * 16] = 0u;
            g_exit = 0u;
            __threadfence();
        }
    }
}

extern "C" void kernel_launch(void* const* d_in, const int* in_sizes, int n_in,
                              void* d_out, int out_size) {
    const float* x   = (const float*)d_in[0];
    const float* Wx  = (const float*)d_in[1];
    const float* Wh  = (const float*)d_in[2];
    const float* b   = (const float*)d_in[3];
    const float* Wfc = (const float*)d_in[4];
    const float* bfc = (const float*)d_in[5];
    float* out = (float*)d_out;
    (void)in_sizes; (void)n_in; (void)out_size;

    cudaFuncSetAttribute(rnn_mma, cudaFuncAttributeMaxDynamicSharedMemorySize, SM_DYN);
    xsplit<<<16384, 256>>>(x);
    rnn_mma<<<NCTA, TPB, SM_DYN>>>(Wx, Wh, b, Wfc, bfc, out);
}